// round 12
// baseline (speedup 1.0000x reference)
#include <cuda_runtime.h>
#include <cuda_fp16.h>
#include <cstdint>

#define NH 12
#define DH 64
#define SEQ 512
#define DM 768
#define MAXB 32

typedef unsigned long long u64;

// ============================ PTX helpers ============================
__device__ __forceinline__ void mma16(float* c, const uint32_t* a, const uint32_t* b) {
    asm volatile(
        "mma.sync.aligned.m16n8k16.row.col.f32.f16.f16.f32 "
        "{%0,%1,%2,%3}, {%4,%5,%6,%7}, {%8,%9}, {%0,%1,%2,%3};"
        : "+f"(c[0]), "+f"(c[1]), "+f"(c[2]), "+f"(c[3])
        : "r"(a[0]), "r"(a[1]), "r"(a[2]), "r"(a[3]), "r"(b[0]), "r"(b[1]));
}
__device__ __forceinline__ void ldsm4(uint32_t& r0, uint32_t& r1, uint32_t& r2,
                                      uint32_t& r3, uint32_t addr) {
    asm volatile("ldmatrix.sync.aligned.m8n8.x4.shared.b16 {%0,%1,%2,%3}, [%4];"
                 : "=r"(r0), "=r"(r1), "=r"(r2), "=r"(r3) : "r"(addr));
}
__device__ __forceinline__ uint32_t pkh2(float lo, float hi) {
    __half2 h = __floats2half2_rn(lo, hi);
    return *(uint32_t*)&h;
}
__device__ __forceinline__ uint32_t smem_u32(const void* p) {
    uint32_t a;
    asm("{ .reg .u64 t; cvta.to.shared.u64 t, %1; cvt.u32.u64 %0, t; }" : "=r"(a) : "l"(p));
    return a;
}
__device__ __forceinline__ void cpa16(uint32_t s, const void* g) {
    asm volatile("cp.async.cg.shared.global [%0], [%1], 16;" :: "r"(s), "l"(g));
}
__device__ __forceinline__ void cpa_commit() {
    asm volatile("cp.async.commit_group;" ::: "memory");
}
template<int N>
__device__ __forceinline__ void cpa_wait() {
    asm volatile("cp.async.wait_group %0;" :: "n"(N) : "memory");
}

// ============================ device scratch ============================
__device__ __align__(128) __half g_q16[(size_t)MAXB * NH * SEQ * DH];   // [s][d]
__device__ __align__(128) __half g_k16[(size_t)MAXB * NH * SEQ * DH];   // [s][d]
__device__ __align__(128) __half g_vt16[(size_t)MAXB * NH * DH * SEQ];  // [d][s], mask folded
__device__ __align__(128) __half g_ah16[(size_t)MAXB * SEQ * DM];       // hidden fp16 [m][k]
__device__ __align__(128) __half g_wth16[(size_t)3 * DM * DM];          // W^T [mat][n][k]

// ---------------------------------------------------------------------------
__global__ void hhalf_kernel(const float* __restrict__ h, int n8) {
    int i = blockIdx.x * blockDim.x + threadIdx.x;
    if (i >= n8) return;
    float4 x = ((const float4*)h)[2 * i];
    float4 y = ((const float4*)h)[2 * i + 1];
    uint4 o;
    o.x = pkh2(x.x, x.y); o.y = pkh2(x.z, x.w);
    o.z = pkh2(y.x, y.y); o.w = pkh2(y.z, y.w);
    ((uint4*)g_ah16)[i] = o;
}

__global__ void wsplit_kernel(const float* __restrict__ Wq,
                              const float* __restrict__ Wk,
                              const float* __restrict__ Wv) {
    __shared__ float th[32][33];
    int mat = blockIdx.z;
    const float* W = (mat == 0) ? Wq : ((mat == 1) ? Wk : Wv);
    int k0 = blockIdx.y * 32, n0 = blockIdx.x * 32;
    int tx = threadIdx.x, ty = threadIdx.y;
#pragma unroll
    for (int j = 0; j < 32; j += 8)
        th[ty + j][tx] = W[(size_t)(k0 + ty + j) * DM + n0 + tx];
    __syncthreads();
    __half* oh = g_wth16 + (size_t)mat * DM * DM;
#pragma unroll
    for (int j = 0; j < 32; j += 8)
        oh[(size_t)(n0 + ty + j) * DM + k0 + tx] = __float2half(th[tx][ty + j]);
}

// ---------------------------------------------------------------------------
// Unified QKV GEMM, fp16 m16n8k16 + ldmatrix, cp.async 2-stage pipeline.
// CTA 128x128; 8 warps 2(m) x 4(n); warp 64x32; K-chunk 64 (4 ksteps).
// A/B smem [row][k] pad-72 halves (LDSM stride 9*16B -> conflict-free).
// Epilogue: +bias; Q/K -> fp16 [s][d]; V -> fp16 mask-folded transposed [d][s].
// ---------------------------------------------------------------------------
#define KCH 64
#define PADG 72
#define ASTAGE_H (128 * PADG)
#define NSTG 2
#define GEMM_SMEM (NSTG * 2 * ASTAGE_H * 2)     // 73728 B

__global__ __launch_bounds__(256) void qkv_gemm_kernel(
    const float* __restrict__ bq, const float* __restrict__ bk,
    const float* __restrict__ bv, const float* __restrict__ mask, int M)
{
    extern __shared__ __half smh[];
    __half* Abase = smh;
    __half* Bbase = smh + NSTG * ASTAGE_H;

    const int tid  = threadIdx.x;
    const int lane = tid & 31;
    const int wid  = tid >> 5;
    const int wm   = wid >> 2;       // 0..1 -> 64 m-rows
    const int wn   = wid & 3;        // 0..3 -> 32 n-cols
    const int lr   = lane >> 2;
    const int lc   = lane & 3;

    const int m0  = blockIdx.x * 128;
    const int yb  = blockIdx.y;
    const int mat = yb / 6;
    const int n0  = (yb % 6) * 128;

    const __half* Wh = g_wth16 + (size_t)mat * DM * DM + (size_t)n0 * DM;

    // cp.async: row tid>>1 (0..127), seg (tid&1)*32 halves; 4 cpa16 per tile
    const int arow = tid >> 1;
    const int asel = (tid & 1) * 32;
    const __half* gA = g_ah16 + (size_t)(m0 + arow) * DM + asel;
    const __half* gB = Wh + (size_t)arow * DM + asel;
    const uint32_t sA = smem_u32(Abase) + (uint32_t)(arow * PADG + asel) * 2;
    const uint32_t sB = smem_u32(Bbase) + (uint32_t)(arow * PADG + asel) * 2;

    // ldmatrix lane mappings
    const int l7 = lane & 7;
    const int aRowL = l7 + ((lane >> 3) & 1) * 8;    // A: g0/g1 m-lo/hi
    const int aColL = ((lane >> 4) & 1) * 8;         //    g2/g3 k-hi
    const int bRowL = l7 + ((lane >> 4) & 1) * 8;    // B: g2/g3 n-hi group
    const int bColL = ((lane >> 3) & 1) * 8;         //    g1/g3 k-hi

#define ISSUE(ch, st)                                                         \
    do {                                                                      \
        const __half* _a = gA + (ch) * KCH;                                   \
        const __half* _b = gB + (ch) * KCH;                                   \
        uint32_t _sa = sA + (st) * (ASTAGE_H * 2);                            \
        uint32_t _sb = sB + (st) * (ASTAGE_H * 2);                            \
        _Pragma("unroll")                                                     \
        for (int _i = 0; _i < 4; _i++) {                                      \
            cpa16(_sa + _i * 16, _a + _i * 8);                                \
            cpa16(_sb + _i * 16, _b + _i * 8);                                \
        }                                                                     \
    } while (0)

    float c[4][4][4];
#pragma unroll
    for (int i = 0; i < 4; i++)
#pragma unroll
        for (int j = 0; j < 4; j++)
#pragma unroll
            for (int q = 0; q < 4; q++) c[i][j][q] = 0.0f;

    const int NCH = DM / KCH;   // 12

    ISSUE(0, 0);
    cpa_commit();

    const uint32_t sbA = smem_u32(Abase);
    const uint32_t sbB = smem_u32(Bbase);

    for (int ch = 0; ch < NCH; ch++) {
        if (ch + 1 < NCH) ISSUE(ch + 1, (ch + 1) & 1);
        cpa_commit();
        cpa_wait<1>();
        __syncthreads();

        const int st = ch & 1;
        uint32_t aAddr[4], bAddr[2];
#pragma unroll
        for (int mt = 0; mt < 4; mt++)
            aAddr[mt] = sbA + (uint32_t)st * (ASTAGE_H * 2)
                      + (uint32_t)((wm * 64 + mt * 16 + aRowL) * PADG + aColL) * 2;
#pragma unroll
        for (int nt2 = 0; nt2 < 2; nt2++)
            bAddr[nt2] = sbB + (uint32_t)st * (ASTAGE_H * 2)
                       + (uint32_t)((wn * 32 + nt2 * 16 + bRowL) * PADG + bColL) * 2;

#pragma unroll
        for (int ks = 0; ks < 4; ks++) {
            const uint32_t off = (uint32_t)ks * 32;   // 16 halves
            uint32_t ah[4][4];
#pragma unroll
            for (int mt = 0; mt < 4; mt++)
                ldsm4(ah[mt][0], ah[mt][1], ah[mt][2], ah[mt][3], aAddr[mt] + off);
            uint32_t bf[2][4];
#pragma unroll
            for (int nt2 = 0; nt2 < 2; nt2++)
                ldsm4(bf[nt2][0], bf[nt2][1], bf[nt2][2], bf[nt2][3], bAddr[nt2] + off);
#pragma unroll
            for (int mt = 0; mt < 4; mt++)
#pragma unroll
                for (int nt2 = 0; nt2 < 2; nt2++) {
                    mma16(c[mt][nt2 * 2 + 0], ah[mt], &bf[nt2][0]);
                    mma16(c[mt][nt2 * 2 + 1], ah[mt], &bf[nt2][2]);
                }
        }
        __syncthreads();
    }
#undef ISSUE

    // epilogue
    const float* bias = (mat == 0) ? bq : ((mat == 1) ? bk : bv);
    __half* dstqk     = (mat == 0) ? g_q16 : g_k16;
    const bool rqk    = (mat != 2);
#pragma unroll
    for (int mt = 0; mt < 4; mt++) {
        const int m = m0 + wm * 64 + mt * 16 + lr;
#pragma unroll
        for (int nt = 0; nt < 4; nt++) {
            const int n = n0 + wn * 32 + nt * 8 + 2 * lc;
            const int hh = n >> 6, d = n & 63;
            const float b0 = bias[n], b1 = bias[n + 1];
#pragma unroll
            for (int half_ = 0; half_ < 2; half_++) {
                const int mm = m + half_ * 8;
                const int bi = mm >> 9, srow = mm & 511;
                float v0 = c[mt][nt][half_ * 2 + 0] + b0;
                float v1 = c[mt][nt][half_ * 2 + 1] + b1;
                if (rqk) {
                    __half2 hv = __floats2half2_rn(v0, v1);
                    *(__half2*)(dstqk + (((size_t)(bi * NH + hh)) * SEQ + srow) * DH + d) = hv;
                } else {
                    const float mv = mask[(size_t)bi * SEQ + srow];
                    __half* o = g_vt16 + ((size_t)(bi * NH + hh) * DH) * SEQ;
                    o[(size_t)d * SEQ + srow]       = __float2half(v0 * mv);
                    o[(size_t)(d + 1) * SEQ + srow] = __float2half(v1 * mv);
                }
            }
        }
    }
}

// ---------------------------------------------------------------------------
// Fused power-law attention, fp16 m16n8k16 + ldmatrix.
// 8 warps x 16 q-rows (q-tile 128); key-tile 32, double-buffered cp.async.
// Q register-resident; phase1 accs pack directly into phase2 A-frags (half2).
// K pad-72 halves, V (transposed [d][s]) pad-40 halves — LDSM conflict-free.
// ---------------------------------------------------------------------------
#define KT 32
#define PADKH 72
#define PADVH 40
#define KBUF_H (KT * PADKH)
#define VBUF_H (DH * PADVH)

__global__ __launch_bounds__(256, 2) void attn_kernel(float* __restrict__ out)
{
    __shared__ __half Ks[2][KBUF_H];
    __shared__ __half Vs[2][VBUF_H];

    const int b  = blockIdx.z;
    const int h  = blockIdx.y;
    const int qt = blockIdx.x * 128;

    const __half* Qg = g_q16 + (((size_t)(b * NH + h)) * SEQ + qt) * DH;
    const __half* Kg = g_k16 + ((size_t)(b * NH + h)) * SEQ * DH;
    const __half* Vg = g_vt16 + ((size_t)(b * NH + h)) * DH * SEQ;   // [d][s]

    const int tid  = threadIdx.x;
    const int lane = tid & 31;
    const int wid  = tid >> 5;
    const int lr   = lane >> 2;
    const int lc   = lane & 3;

    // cp.async mappings
    const int krow = tid >> 3;
    const int ksg  = (tid & 7) * 8;
    const __half* KgR = Kg + (size_t)krow * DH + ksg;
    const uint32_t sK = smem_u32(&Ks[0][0]) + (uint32_t)(krow * PADKH + ksg) * 2;

    const int vrow = tid >> 2;
    const int vsg  = (tid & 3) * 8;
    const __half* VgR = Vg + (size_t)vrow * SEQ + vsg;
    const uint32_t sV = smem_u32(&Vs[0][0]) + (uint32_t)(vrow * PADVH + vsg) * 2;

    // ldmatrix lane mapping (B-style): rows via g-hi bit, cols via g-lo bit
    const int l7 = lane & 7;
    const int bRowL = l7 + ((lane >> 4) & 1) * 8;
    const int bColL = ((lane >> 3) & 1) * 8;

#define ISSKV(kt_, buf_)                                                      \
    do {                                                                      \
        const __half* _k = KgR + (size_t)(kt_) * KT * DH;                     \
        const __half* _v = VgR + (kt_) * KT;                                  \
        uint32_t _ok = (uint32_t)(buf_) * (KBUF_H * 2);                       \
        uint32_t _ov = (uint32_t)(buf_) * (VBUF_H * 2);                       \
        cpa16(sK + _ok, _k);                                                  \
        cpa16(sV + _ov, _v);                                                  \
        cpa_commit();                                                         \
    } while (0)

    ISSKV(0, 0);

    // Q fragments: 16 rows per warp, register-resident
    uint32_t qf[4][4];
    {
        const int r0 = wid * 16 + lr;
#pragma unroll
        for (int ks = 0; ks < 4; ks++) {
            const int dbase = ks * 16 + 2 * lc;
            qf[ks][0] = *(const uint32_t*)(Qg + (size_t)r0 * DH + dbase);
            qf[ks][1] = *(const uint32_t*)(Qg + (size_t)(r0 + 8) * DH + dbase);
            qf[ks][2] = *(const uint32_t*)(Qg + (size_t)r0 * DH + dbase + 8);
            qf[ks][3] = *(const uint32_t*)(Qg + (size_t)(r0 + 8) * DH + dbase + 8);
        }
    }

    // ldmatrix base addresses (per buffer added in-loop)
    const uint32_t kBase = smem_u32(&Ks[0][0]);
    const uint32_t vBase = smem_u32(&Vs[0][0]);

    float o[8][4];
#pragma unroll
    for (int j = 0; j < 8; j++)
#pragma unroll
        for (int q = 0; q < 4; q++) o[j][q] = 0.0f;
    float den0 = 0.0f, den1 = 0.0f;

    const int NKT = SEQ / KT;   // 16

    for (int kt = 0; kt < NKT; kt++) {
        const int buf = kt & 1;
        if (kt + 1 < NKT) {
            ISSKV(kt + 1, buf ^ 1);
            cpa_wait<1>();
        } else {
            cpa_wait<0>();
        }
        __syncthreads();

        const uint32_t kb = kBase + (uint32_t)buf * (KBUF_H * 2);
        const uint32_t vb = vBase + (uint32_t)buf * (VBUF_H * 2);

        // ---- phase 1: S = Q K^T ----
        float s[4][4];
#pragma unroll
        for (int j = 0; j < 4; j++)
#pragma unroll
            for (int q = 0; q < 4; q++) s[j][q] = 0.0f;

        uint32_t kAddr0 = kb + (uint32_t)((bRowL) * PADKH + bColL) * 2;
        uint32_t kAddr1 = kb + (uint32_t)((16 + bRowL) * PADKH + bColL) * 2;
#pragma unroll
        for (int ks = 0; ks < 4; ks++) {
            const uint32_t off = (uint32_t)ks * 32;
            uint32_t f0[4], f1[4];
            ldsm4(f0[0], f0[1], f0[2], f0[3], kAddr0 + off);
            ldsm4(f1[0], f1[1], f1[2], f1[3], kAddr1 + off);
            mma16(s[0], qf[ks], &f0[0]);
            mma16(s[1], qf[ks], &f0[2]);
            mma16(s[2], qf[ks], &f1[0]);
            mma16(s[3], qf[ks], &f1[2]);
        }

        // ---- transform ----
        float u[4][4];
#pragma unroll
        for (int nt = 0; nt < 4; nt++) {
#pragma unroll
            for (int q = 0; q < 4; q++) {
                float t = fmaf(s[nt][q], 0.125f, 5.0f);
                u[nt][q] = t * t;
            }
            den0 += u[nt][0] + u[nt][1];
            den1 += u[nt][2] + u[nt][3];
        }

        // ---- phase 2: O += U * V ----
#pragma unroll
        for (int ksp = 0; ksp < 2; ksp++) {
            uint32_t af[4];
            af[0] = pkh2(u[2 * ksp][0],     u[2 * ksp][1]);
            af[1] = pkh2(u[2 * ksp][2],     u[2 * ksp][3]);
            af[2] = pkh2(u[2 * ksp + 1][0], u[2 * ksp + 1][1]);
            af[3] = pkh2(u[2 * ksp + 1][2], u[2 * ksp + 1][3]);
            const uint32_t coff = (uint32_t)ksp * 32;
#pragma unroll
            for (int dtp = 0; dtp < 4; dtp++) {
                uint32_t vAddr = vb + (uint32_t)((dtp * 16 + bRowL) * PADVH + bColL) * 2 + coff;
                uint32_t vf[4];
                ldsm4(vf[0], vf[1], vf[2], vf[3], vAddr);
                mma16(o[dtp * 2 + 0], af, &vf[0]);
                mma16(o[dtp * 2 + 1], af, &vf[2]);
            }
        }
        __syncthreads();
    }
#undef ISSKV

    // quad-reduce den
    den0 += __shfl_xor_sync(0xFFFFFFFFu, den0, 1);
    den0 += __shfl_xor_sync(0xFFFFFFFFu, den0, 2);
    den1 += __shfl_xor_sync(0xFFFFFFFFu, den1, 1);
    den1 += __shfl_xor_sync(0xFFFFFFFFu, den1, 2);

    const float inv0 = 1.0f / (den0 + 1e-10f);
    const float inv1 = 1.0f / (den1 + 1e-10f);
    const int r0 = qt + wid * 16 + lr;
    float* o0 = out + ((size_t)b * SEQ + r0) * DM + h * DH;
    float* o1 = out + ((size_t)b * SEQ + r0 + 8) * DM + h * DH;
#pragma unroll
    for (int dt = 0; dt < 8; dt++) {
        const int d = dt * 8 + 2 * lc;
        *(float2*)(o0 + d) = make_float2(o[dt][0] * inv0, o[dt][1] * inv0);
        *(float2*)(o1 + d) = make_float2(o[dt][2] * inv1, o[dt][3] * inv1);
    }
}

// ---------------------------------------------------------------------------
extern "C" void kernel_launch(void* const* d_in, const int* in_sizes, int n_in,
                              void* d_out, int out_size)
{
    const float* hidden = (const float*)d_in[0];
    const float* mask   = (const float*)d_in[1];
    const float* Wq     = (const float*)d_in[2];
    const float* bq     = (const float*)d_in[3];
    const float* Wk     = (const float*)d_in[4];
    const float* bk     = (const float*)d_in[5];
    const float* Wv     = (const float*)d_in[6];
    const float* bv     = (const float*)d_in[7];
    float* out = (float*)d_out;

    const int BS = in_sizes[1];
    const int B  = BS / SEQ;
    const int M  = BS;

    cudaFuncSetAttribute(qkv_gemm_kernel,
                         cudaFuncAttributeMaxDynamicSharedMemorySize, GEMM_SMEM);

    int n8 = M * DM / 8;
    hhalf_kernel<<<(n8 + 255) / 256, 256>>>(hidden, n8);

    dim3 gw(DM / 32, DM / 32, 3);
    wsplit_kernel<<<gw, dim3(32, 8)>>>(Wq, Wk, Wv);

    dim3 gm(M / 128, 18);
    qkv_gemm_kernel<<<gm, 256, GEMM_SMEM>>>(bq, bk, bv, mask, M);

    dim3 g2(SEQ / 128, NH, B);
    attn_kernel<<<g2, 256>>>(out);
}

// round 13
// speedup vs baseline: 1.0438x; 1.0438x over previous
#include <cuda_runtime.h>
#include <cuda_fp16.h>
#include <cstdint>

#define NH 12
#define DH 64
#define SEQ 512
#define DM 768
#define MAXB 32

typedef unsigned long long u64;

// ============================ PTX helpers ============================
__device__ __forceinline__ void mma16(float* c, const uint32_t* a, const uint32_t* b) {
    asm volatile(
        "mma.sync.aligned.m16n8k16.row.col.f32.f16.f16.f32 "
        "{%0,%1,%2,%3}, {%4,%5,%6,%7}, {%8,%9}, {%0,%1,%2,%3};"
        : "+f"(c[0]), "+f"(c[1]), "+f"(c[2]), "+f"(c[3])
        : "r"(a[0]), "r"(a[1]), "r"(a[2]), "r"(a[3]), "r"(b[0]), "r"(b[1]));
}
__device__ __forceinline__ void ldsm4(uint32_t& r0, uint32_t& r1, uint32_t& r2,
                                      uint32_t& r3, uint32_t addr) {
    asm volatile("ldmatrix.sync.aligned.m8n8.x4.shared.b16 {%0,%1,%2,%3}, [%4];"
                 : "=r"(r0), "=r"(r1), "=r"(r2), "=r"(r3) : "r"(addr));
}
__device__ __forceinline__ uint32_t pkh2(float lo, float hi) {
    __half2 h = __floats2half2_rn(lo, hi);
    return *(uint32_t*)&h;
}
__device__ __forceinline__ uint32_t smem_u32(const void* p) {
    uint32_t a;
    asm("{ .reg .u64 t; cvta.to.shared.u64 t, %1; cvt.u32.u64 %0, t; }" : "=r"(a) : "l"(p));
    return a;
}
__device__ __forceinline__ void cpa16(uint32_t s, const void* g) {
    asm volatile("cp.async.cg.shared.global [%0], [%1], 16;" :: "r"(s), "l"(g));
}
__device__ __forceinline__ void cpa_commit() {
    asm volatile("cp.async.commit_group;" ::: "memory");
}
template<int N>
__device__ __forceinline__ void cpa_wait() {
    asm volatile("cp.async.wait_group %0;" :: "n"(N) : "memory");
}

// ============================ device scratch ============================
__device__ __align__(128) __half g_q16[(size_t)MAXB * NH * SEQ * DH];   // [s][d]
__device__ __align__(128) __half g_k16[(size_t)MAXB * NH * SEQ * DH];   // [s][d]
__device__ __align__(128) __half g_vt16[(size_t)MAXB * NH * DH * SEQ];  // [d][s], mask folded
__device__ __align__(128) __half g_ah16[(size_t)MAXB * SEQ * DM];       // hidden fp16 [m][k]
__device__ __align__(128) __half g_wth16[(size_t)3 * DM * DM];          // W^T [mat][n][k]

// ---------------------------------------------------------------------------
__global__ void hhalf_kernel(const float* __restrict__ h, int n8) {
    int i = blockIdx.x * blockDim.x + threadIdx.x;
    if (i >= n8) return;
    float4 x = ((const float4*)h)[2 * i];
    float4 y = ((const float4*)h)[2 * i + 1];
    uint4 o;
    o.x = pkh2(x.x, x.y); o.y = pkh2(x.z, x.w);
    o.z = pkh2(y.x, y.y); o.w = pkh2(y.z, y.w);
    ((uint4*)g_ah16)[i] = o;
}

__global__ void wsplit_kernel(const float* __restrict__ Wq,
                              const float* __restrict__ Wk,
                              const float* __restrict__ Wv) {
    __shared__ float th[32][33];
    int mat = blockIdx.z;
    const float* W = (mat == 0) ? Wq : ((mat == 1) ? Wk : Wv);
    int k0 = blockIdx.y * 32, n0 = blockIdx.x * 32;
    int tx = threadIdx.x, ty = threadIdx.y;
#pragma unroll
    for (int j = 0; j < 32; j += 8)
        th[ty + j][tx] = W[(size_t)(k0 + ty + j) * DM + n0 + tx];
    __syncthreads();
    __half* oh = g_wth16 + (size_t)mat * DM * DM;
#pragma unroll
    for (int j = 0; j < 32; j += 8)
        oh[(size_t)(n0 + ty + j) * DM + k0 + tx] = __float2half(th[tx][ty + j]);
}

// ---------------------------------------------------------------------------
// Unified QKV GEMM, fp16 m16n8k16 + ldmatrix, cp.async 3-stage pipeline.
// CTA 128x128; 8 warps 2(m) x 4(n); warp 64x32; K-chunk 32 (2 ksteps of k16).
// A/B smem [row][k] pad-40 halves (LDSM row-stride 5 granules -> conflict-free).
// Epilogue: +bias; Q/K -> fp16 [s][d]; V -> fp16 mask-folded transposed [d][s].
// ---------------------------------------------------------------------------
#define PADG 40
#define ASTAGE_H (128 * PADG)
#define NSTG 3
#define GEMM_SMEM (NSTG * 2 * ASTAGE_H * 2)     // 61440 B

__global__ __launch_bounds__(256) void qkv_gemm_kernel(
    const float* __restrict__ bq, const float* __restrict__ bk,
    const float* __restrict__ bv, const float* __restrict__ mask, int M)
{
    extern __shared__ __half smh[];
    __half* Abase = smh;
    __half* Bbase = smh + NSTG * ASTAGE_H;

    const int tid  = threadIdx.x;
    const int lane = tid & 31;
    const int wid  = tid >> 5;
    const int wm   = wid >> 2;       // 0..1 -> 64 m-rows
    const int wn   = wid & 3;        // 0..3 -> 32 n-cols
    const int lr   = lane >> 2;
    const int lc   = lane & 3;

    const int m0  = blockIdx.x * 128;
    const int yb  = blockIdx.y;
    const int mat = yb / 6;
    const int n0  = (yb % 6) * 128;

    const __half* Wh = g_wth16 + (size_t)mat * DM * DM + (size_t)n0 * DM;

    // cp.async: row tid>>1 (0..127), seg (tid&1)*16 halves; 2 cpa16 per tile
    const int arow = tid >> 1;
    const int asel = (tid & 1) * 16;
    const __half* gA = g_ah16 + (size_t)(m0 + arow) * DM + asel;
    const __half* gB = Wh + (size_t)arow * DM + asel;
    const uint32_t sA = smem_u32(Abase) + (uint32_t)(arow * PADG + asel) * 2;
    const uint32_t sB = smem_u32(Bbase) + (uint32_t)(arow * PADG + asel) * 2;

    // ldmatrix lane mappings
    const int l7 = lane & 7;
    const int aRowL = l7 + ((lane >> 3) & 1) * 8;    // A: g0/g1 m-lo/hi
    const int aColL = ((lane >> 4) & 1) * 8;         //    g2/g3 k-hi
    const int bRowL = l7 + ((lane >> 4) & 1) * 8;    // B: g2/g3 n-hi group
    const int bColL = ((lane >> 3) & 1) * 8;         //    g1/g3 k-hi

#define ISSUE(ch, st)                                                         \
    do {                                                                      \
        const __half* _a = gA + (ch) * 32;                                    \
        const __half* _b = gB + (ch) * 32;                                    \
        uint32_t _sa = sA + (st) * (ASTAGE_H * 2);                            \
        uint32_t _sb = sB + (st) * (ASTAGE_H * 2);                            \
        cpa16(_sa, _a);      cpa16(_sa + 16, _a + 8);                         \
        cpa16(_sb, _b);      cpa16(_sb + 16, _b + 8);                         \
    } while (0)

    float c[4][4][4];
#pragma unroll
    for (int i = 0; i < 4; i++)
#pragma unroll
        for (int j = 0; j < 4; j++)
#pragma unroll
            for (int q = 0; q < 4; q++) c[i][j][q] = 0.0f;

    const int NCH = DM / 32;   // 24

#pragma unroll
    for (int p = 0; p < NSTG - 1; p++) {
        ISSUE(p, p);
        cpa_commit();
    }

    const uint32_t sbA = smem_u32(Abase);
    const uint32_t sbB = smem_u32(Bbase);

    for (int ch = 0; ch < NCH; ch++) {
        const int pre = ch + NSTG - 1;
        if (pre < NCH) ISSUE(pre, pre % NSTG);
        cpa_commit();
        cpa_wait<NSTG - 1>();
        __syncthreads();

        const int st = ch % NSTG;
        uint32_t aAddr[4], bAddr[2];
#pragma unroll
        for (int mt = 0; mt < 4; mt++)
            aAddr[mt] = sbA + (uint32_t)st * (ASTAGE_H * 2)
                      + (uint32_t)((wm * 64 + mt * 16 + aRowL) * PADG + aColL) * 2;
#pragma unroll
        for (int nt2 = 0; nt2 < 2; nt2++)
            bAddr[nt2] = sbB + (uint32_t)st * (ASTAGE_H * 2)
                       + (uint32_t)((wn * 32 + nt2 * 16 + bRowL) * PADG + bColL) * 2;

#pragma unroll
        for (int ks = 0; ks < 2; ks++) {
            const uint32_t off = (uint32_t)ks * 32;   // 16 halves
            uint32_t ah[4][4];
#pragma unroll
            for (int mt = 0; mt < 4; mt++)
                ldsm4(ah[mt][0], ah[mt][1], ah[mt][2], ah[mt][3], aAddr[mt] + off);
            uint32_t bf[2][4];
#pragma unroll
            for (int nt2 = 0; nt2 < 2; nt2++)
                ldsm4(bf[nt2][0], bf[nt2][1], bf[nt2][2], bf[nt2][3], bAddr[nt2] + off);
#pragma unroll
            for (int mt = 0; mt < 4; mt++)
#pragma unroll
                for (int nt2 = 0; nt2 < 2; nt2++) {
                    mma16(c[mt][nt2 * 2 + 0], ah[mt], &bf[nt2][0]);
                    mma16(c[mt][nt2 * 2 + 1], ah[mt], &bf[nt2][2]);
                }
        }
        __syncthreads();
    }
#undef ISSUE

    // epilogue
    const float* bias = (mat == 0) ? bq : ((mat == 1) ? bk : bv);
    __half* dstqk     = (mat == 0) ? g_q16 : g_k16;
    const bool rqk    = (mat != 2);
#pragma unroll
    for (int mt = 0; mt < 4; mt++) {
        const int m = m0 + wm * 64 + mt * 16 + lr;
#pragma unroll
        for (int nt = 0; nt < 4; nt++) {
            const int n = n0 + wn * 32 + nt * 8 + 2 * lc;
            const int hh = n >> 6, d = n & 63;
            const float b0 = bias[n], b1 = bias[n + 1];
#pragma unroll
            for (int half_ = 0; half_ < 2; half_++) {
                const int mm = m + half_ * 8;
                const int bi = mm >> 9, srow = mm & 511;
                float v0 = c[mt][nt][half_ * 2 + 0] + b0;
                float v1 = c[mt][nt][half_ * 2 + 1] + b1;
                if (rqk) {
                    __half2 hv = __floats2half2_rn(v0, v1);
                    *(__half2*)(dstqk + (((size_t)(bi * NH + hh)) * SEQ + srow) * DH + d) = hv;
                } else {
                    const float mv = mask[(size_t)bi * SEQ + srow];
                    __half* o = g_vt16 + ((size_t)(bi * NH + hh) * DH) * SEQ;
                    o[(size_t)d * SEQ + srow]       = __float2half(v0 * mv);
                    o[(size_t)(d + 1) * SEQ + srow] = __float2half(v1 * mv);
                }
            }
        }
    }
}

// ---------------------------------------------------------------------------
// Fused power-law attention (unchanged from R12): fp16 m16n8k16 + ldmatrix.
// 8 warps x 16 q-rows (q-tile 128); key-tile 32, double-buffered cp.async.
// ---------------------------------------------------------------------------
#define KT 32
#define PADKH 72
#define PADVH 40
#define KBUF_H (KT * PADKH)
#define VBUF_H (DH * PADVH)

__global__ __launch_bounds__(256, 2) void attn_kernel(float* __restrict__ out)
{
    __shared__ __half Ks[2][KBUF_H];
    __shared__ __half Vs[2][VBUF_H];

    const int b  = blockIdx.z;
    const int h  = blockIdx.y;
    const int qt = blockIdx.x * 128;

    const __half* Qg = g_q16 + (((size_t)(b * NH + h)) * SEQ + qt) * DH;
    const __half* Kg = g_k16 + ((size_t)(b * NH + h)) * SEQ * DH;
    const __half* Vg = g_vt16 + ((size_t)(b * NH + h)) * DH * SEQ;   // [d][s]

    const int tid  = threadIdx.x;
    const int lane = tid & 31;
    const int wid  = tid >> 5;
    const int lr   = lane >> 2;
    const int lc   = lane & 3;

    const int krow = tid >> 3;
    const int ksg  = (tid & 7) * 8;
    const __half* KgR = Kg + (size_t)krow * DH + ksg;
    const uint32_t sK = smem_u32(&Ks[0][0]) + (uint32_t)(krow * PADKH + ksg) * 2;

    const int vrow = tid >> 2;
    const int vsg  = (tid & 3) * 8;
    const __half* VgR = Vg + (size_t)vrow * SEQ + vsg;
    const uint32_t sV = smem_u32(&Vs[0][0]) + (uint32_t)(vrow * PADVH + vsg) * 2;

    const int l7 = lane & 7;
    const int bRowL = l7 + ((lane >> 4) & 1) * 8;
    const int bColL = ((lane >> 3) & 1) * 8;

#define ISSKV(kt_, buf_)                                                      \
    do {                                                                      \
        const __half* _k = KgR + (size_t)(kt_) * KT * DH;                     \
        const __half* _v = VgR + (kt_) * KT;                                  \
        uint32_t _ok = (uint32_t)(buf_) * (KBUF_H * 2);                       \
        uint32_t _ov = (uint32_t)(buf_) * (VBUF_H * 2);                       \
        cpa16(sK + _ok, _k);                                                  \
        cpa16(sV + _ov, _v);                                                  \
        cpa_commit();                                                         \
    } while (0)

    ISSKV(0, 0);

    uint32_t qf[4][4];
    {
        const int r0 = wid * 16 + lr;
#pragma unroll
        for (int ks = 0; ks < 4; ks++) {
            const int dbase = ks * 16 + 2 * lc;
            qf[ks][0] = *(const uint32_t*)(Qg + (size_t)r0 * DH + dbase);
            qf[ks][1] = *(const uint32_t*)(Qg + (size_t)(r0 + 8) * DH + dbase);
            qf[ks][2] = *(const uint32_t*)(Qg + (size_t)r0 * DH + dbase + 8);
            qf[ks][3] = *(const uint32_t*)(Qg + (size_t)(r0 + 8) * DH + dbase + 8);
        }
    }

    const uint32_t kBase = smem_u32(&Ks[0][0]);
    const uint32_t vBase = smem_u32(&Vs[0][0]);

    float o[8][4];
#pragma unroll
    for (int j = 0; j < 8; j++)
#pragma unroll
        for (int q = 0; q < 4; q++) o[j][q] = 0.0f;
    float den0 = 0.0f, den1 = 0.0f;

    const int NKT = SEQ / KT;   // 16

    for (int kt = 0; kt < NKT; kt++) {
        const int buf = kt & 1;
        if (kt + 1 < NKT) {
            ISSKV(kt + 1, buf ^ 1);
            cpa_wait<1>();
        } else {
            cpa_wait<0>();
        }
        __syncthreads();

        const uint32_t kb = kBase + (uint32_t)buf * (KBUF_H * 2);
        const uint32_t vb = vBase + (uint32_t)buf * (VBUF_H * 2);

        float s[4][4];
#pragma unroll
        for (int j = 0; j < 4; j++)
#pragma unroll
            for (int q = 0; q < 4; q++) s[j][q] = 0.0f;

        uint32_t kAddr0 = kb + (uint32_t)((bRowL) * PADKH + bColL) * 2;
        uint32_t kAddr1 = kb + (uint32_t)((16 + bRowL) * PADKH + bColL) * 2;
#pragma unroll
        for (int ks = 0; ks < 4; ks++) {
            const uint32_t off = (uint32_t)ks * 32;
            uint32_t f0[4], f1[4];
            ldsm4(f0[0], f0[1], f0[2], f0[3], kAddr0 + off);
            ldsm4(f1[0], f1[1], f1[2], f1[3], kAddr1 + off);
            mma16(s[0], qf[ks], &f0[0]);
            mma16(s[1], qf[ks], &f0[2]);
            mma16(s[2], qf[ks], &f1[0]);
            mma16(s[3], qf[ks], &f1[2]);
        }

        float u[4][4];
#pragma unroll
        for (int nt = 0; nt < 4; nt++) {
#pragma unroll
            for (int q = 0; q < 4; q++) {
                float t = fmaf(s[nt][q], 0.125f, 5.0f);
                u[nt][q] = t * t;
            }
            den0 += u[nt][0] + u[nt][1];
            den1 += u[nt][2] + u[nt][3];
        }

#pragma unroll
        for (int ksp = 0; ksp < 2; ksp++) {
            uint32_t af[4];
            af[0] = pkh2(u[2 * ksp][0],     u[2 * ksp][1]);
            af[1] = pkh2(u[2 * ksp][2],     u[2 * ksp][3]);
            af[2] = pkh2(u[2 * ksp + 1][0], u[2 * ksp + 1][1]);
            af[3] = pkh2(u[2 * ksp + 1][2], u[2 * ksp + 1][3]);
            const uint32_t coff = (uint32_t)ksp * 32;
#pragma unroll
            for (int dtp = 0; dtp < 4; dtp++) {
                uint32_t vAddr = vb + (uint32_t)((dtp * 16 + bRowL) * PADVH + bColL) * 2 + coff;
                uint32_t vf[4];
                ldsm4(vf[0], vf[1], vf[2], vf[3], vAddr);
                mma16(o[dtp * 2 + 0], af, &vf[0]);
                mma16(o[dtp * 2 + 1], af, &vf[2]);
            }
        }
        __syncthreads();
    }
#undef ISSKV

    den0 += __shfl_xor_sync(0xFFFFFFFFu, den0, 1);
    den0 += __shfl_xor_sync(0xFFFFFFFFu, den0, 2);
    den1 += __shfl_xor_sync(0xFFFFFFFFu, den1, 1);
    den1 += __shfl_xor_sync(0xFFFFFFFFu, den1, 2);

    const float inv0 = 1.0f / (den0 + 1e-10f);
    const float inv1 = 1.0f / (den1 + 1e-10f);
    const int r0 = qt + wid * 16 + lr;
    float* o0 = out + ((size_t)b * SEQ + r0) * DM + h * DH;
    float* o1 = out + ((size_t)b * SEQ + r0 + 8) * DM + h * DH;
#pragma unroll
    for (int dt = 0; dt < 8; dt++) {
        const int d = dt * 8 + 2 * lc;
        *(float2*)(o0 + d) = make_float2(o[dt][0] * inv0, o[dt][1] * inv0);
        *(float2*)(o1 + d) = make_float2(o[dt][2] * inv1, o[dt][3] * inv1);
    }
}

// ---------------------------------------------------------------------------
extern "C" void kernel_launch(void* const* d_in, const int* in_sizes, int n_in,
                              void* d_out, int out_size)
{
    const float* hidden = (const float*)d_in[0];
    const float* mask   = (const float*)d_in[1];
    const float* Wq     = (const float*)d_in[2];
    const float* bq     = (const float*)d_in[3];
    const float* Wk     = (const float*)d_in[4];
    const float* bk     = (const float*)d_in[5];
    const float* Wv     = (const float*)d_in[6];
    const float* bv     = (const float*)d_in[7];
    float* out = (float*)d_out;

    const int BS = in_sizes[1];
    const int B  = BS / SEQ;
    const int M  = BS;

    cudaFuncSetAttribute(qkv_gemm_kernel,
                         cudaFuncAttributeMaxDynamicSharedMemorySize, GEMM_SMEM);

    int n8 = M * DM / 8;
    hhalf_kernel<<<(n8 + 255) / 256, 256>>>(hidden, n8);

    dim3 gw(DM / 32, DM / 32, 3);
    wsplit_kernel<<<gw, dim3(32, 8)>>>(Wq, Wk, Wv);

    dim3 gm(M / 128, 18);
    qkv_gemm_kernel<<<gm, 256, GEMM_SMEM>>>(bq, bk, bv, mask, M);

    dim3 g2(SEQ / 128, NH, B);
    attn_kernel<<<g2, 256>>>(out);
}

// round 14
// speedup vs baseline: 1.0824x; 1.0369x over previous
#include <cuda_runtime.h>
#include <cuda_fp16.h>
#include <cstdint>

#define NH 12
#define DH 64
#define SEQ 512
#define DM 768
#define MAXB 32

typedef unsigned long long u64;

// ============================ PTX helpers ============================
__device__ __forceinline__ void mma16(float* c, const uint32_t* a, const uint32_t* b) {
    asm volatile(
        "mma.sync.aligned.m16n8k16.row.col.f32.f16.f16.f32 "
        "{%0,%1,%2,%3}, {%4,%5,%6,%7}, {%8,%9}, {%0,%1,%2,%3};"
        : "+f"(c[0]), "+f"(c[1]), "+f"(c[2]), "+f"(c[3])
        : "r"(a[0]), "r"(a[1]), "r"(a[2]), "r"(a[3]), "r"(b[0]), "r"(b[1]));
}
__device__ __forceinline__ void ldsm4(uint32_t& r0, uint32_t& r1, uint32_t& r2,
                                      uint32_t& r3, uint32_t addr) {
    asm volatile("ldmatrix.sync.aligned.m8n8.x4.shared.b16 {%0,%1,%2,%3}, [%4];"
                 : "=r"(r0), "=r"(r1), "=r"(r2), "=r"(r3) : "r"(addr));
}
__device__ __forceinline__ uint32_t pkh2(float lo, float hi) {
    __half2 h = __floats2half2_rn(lo, hi);
    return *(uint32_t*)&h;
}
__device__ __forceinline__ uint32_t smem_u32(const void* p) {
    uint32_t a;
    asm("{ .reg .u64 t; cvta.to.shared.u64 t, %1; cvt.u32.u64 %0, t; }" : "=r"(a) : "l"(p));
    return a;
}
__device__ __forceinline__ void cpa16(uint32_t s, const void* g) {
    asm volatile("cp.async.cg.shared.global [%0], [%1], 16;" :: "r"(s), "l"(g));
}
__device__ __forceinline__ void cpa_commit() {
    asm volatile("cp.async.commit_group;" ::: "memory");
}
template<int N>
__device__ __forceinline__ void cpa_wait() {
    asm volatile("cp.async.wait_group %0;" :: "n"(N) : "memory");
}

// ============================ device scratch ============================
__device__ __align__(128) __half g_q16[(size_t)MAXB * NH * SEQ * DH];   // [s][d]
__device__ __align__(128) __half g_k16[(size_t)MAXB * NH * SEQ * DH];   // [s][d]
__device__ __align__(128) __half g_vt16[(size_t)MAXB * NH * DH * SEQ];  // [d][s], mask folded
__device__ __align__(128) __half g_ah16[(size_t)MAXB * SEQ * DM];       // hidden fp16 [m][k]
__device__ __align__(128) __half g_wth16[(size_t)3 * DM * DM];          // W^T [mat][n][k]

// ---------------------------------------------------------------------------
__global__ void hhalf_kernel(const float* __restrict__ h, int n8) {
    int i = blockIdx.x * blockDim.x + threadIdx.x;
    if (i >= n8) return;
    float4 x = ((const float4*)h)[2 * i];
    float4 y = ((const float4*)h)[2 * i + 1];
    uint4 o;
    o.x = pkh2(x.x, x.y); o.y = pkh2(x.z, x.w);
    o.z = pkh2(y.x, y.y); o.w = pkh2(y.z, y.w);
    ((uint4*)g_ah16)[i] = o;
}

__global__ void wsplit_kernel(const float* __restrict__ Wq,
                              const float* __restrict__ Wk,
                              const float* __restrict__ Wv) {
    __shared__ float th[32][33];
    int mat = blockIdx.z;
    const float* W = (mat == 0) ? Wq : ((mat == 1) ? Wk : Wv);
    int k0 = blockIdx.y * 32, n0 = blockIdx.x * 32;
    int tx = threadIdx.x, ty = threadIdx.y;
#pragma unroll
    for (int j = 0; j < 32; j += 8)
        th[ty + j][tx] = W[(size_t)(k0 + ty + j) * DM + n0 + tx];
    __syncthreads();
    __half* oh = g_wth16 + (size_t)mat * DM * DM;
#pragma unroll
    for (int j = 0; j < 32; j += 8)
        oh[(size_t)(n0 + ty + j) * DM + k0 + tx] = __float2half(th[tx][ty + j]);
}

// ---------------------------------------------------------------------------
// Unified QKV GEMM, fp16 m16n8k16 + ldmatrix, cp.async 4-stage pipeline,
// ONE syncthreads per chunk (wait -> sync -> issue -> compute).
// CTA 128x128; 8 warps 2(m) x 4(n); warp 64x32; K-chunk 32 (2 ksteps of k16).
// A/B smem [row][k] pad-40 halves (LDSM row-stride 5 granules -> conflict-free).
// Epilogue: +bias; Q/K -> fp16 [s][d]; V -> fp16 mask-folded transposed [d][s].
// ---------------------------------------------------------------------------
#define PADG 40
#define ASTAGE_H (128 * PADG)
#define NSTG 4
#define GEMM_SMEM (NSTG * 2 * ASTAGE_H * 2)     // 81920 B

__global__ __launch_bounds__(256) void qkv_gemm_kernel(
    const float* __restrict__ bq, const float* __restrict__ bk,
    const float* __restrict__ bv, const float* __restrict__ mask, int M)
{
    extern __shared__ __half smh[];
    __half* Abase = smh;
    __half* Bbase = smh + NSTG * ASTAGE_H;

    const int tid  = threadIdx.x;
    const int lane = tid & 31;
    const int wid  = tid >> 5;
    const int wm   = wid >> 2;       // 0..1 -> 64 m-rows
    const int wn   = wid & 3;        // 0..3 -> 32 n-cols
    const int lr   = lane >> 2;
    const int lc   = lane & 3;

    const int m0  = blockIdx.x * 128;
    const int yb  = blockIdx.y;
    const int mat = yb / 6;
    const int n0  = (yb % 6) * 128;

    const __half* Wh = g_wth16 + (size_t)mat * DM * DM + (size_t)n0 * DM;

    // cp.async: row tid>>1 (0..127), seg (tid&1)*16 halves; 2 cpa16 per tile
    const int arow = tid >> 1;
    const int asel = (tid & 1) * 16;
    const __half* gA = g_ah16 + (size_t)(m0 + arow) * DM + asel;
    const __half* gB = Wh + (size_t)arow * DM + asel;
    const uint32_t sA = smem_u32(Abase) + (uint32_t)(arow * PADG + asel) * 2;
    const uint32_t sB = smem_u32(Bbase) + (uint32_t)(arow * PADG + asel) * 2;

    // ldmatrix lane mappings
    const int l7 = lane & 7;
    const int aRowL = l7 + ((lane >> 3) & 1) * 8;    // A: g0/g1 m-lo/hi
    const int aColL = ((lane >> 4) & 1) * 8;         //    g2/g3 k-hi
    const int bRowL = l7 + ((lane >> 4) & 1) * 8;    // B: g2/g3 n-hi group
    const int bColL = ((lane >> 3) & 1) * 8;         //    g1/g3 k-hi

#define ISSUE(ch, st)                                                         \
    do {                                                                      \
        const __half* _a = gA + (ch) * 32;                                    \
        const __half* _b = gB + (ch) * 32;                                    \
        uint32_t _sa = sA + (st) * (ASTAGE_H * 2);                            \
        uint32_t _sb = sB + (st) * (ASTAGE_H * 2);                            \
        cpa16(_sa, _a);      cpa16(_sa + 16, _a + 8);                         \
        cpa16(_sb, _b);      cpa16(_sb + 16, _b + 8);                         \
    } while (0)

    float c[4][4][4];
#pragma unroll
    for (int i = 0; i < 4; i++)
#pragma unroll
        for (int j = 0; j < 4; j++)
#pragma unroll
            for (int q = 0; q < 4; q++) c[i][j][q] = 0.0f;

    const int NCH = DM / 32;   // 24

#pragma unroll
    for (int p = 0; p < NSTG - 1; p++) {
        ISSUE(p, p);
        cpa_commit();
    }

    const uint32_t sbA = smem_u32(Abase);
    const uint32_t sbB = smem_u32(Bbase);

    for (int ch = 0; ch < NCH; ch++) {
        cpa_wait<NSTG - 2>();        // chunk ch arrived (positional)
        __syncthreads();             // + all warps done reading stage being reused

        const int pre = ch + NSTG - 1;
        if (pre < NCH) ISSUE(pre, pre % NSTG);
        cpa_commit();                // unconditional: keeps wait_group positional math exact

        const int st = ch % NSTG;
        uint32_t aAddr[4], bAddr[2];
#pragma unroll
        for (int mt = 0; mt < 4; mt++)
            aAddr[mt] = sbA + (uint32_t)st * (ASTAGE_H * 2)
                      + (uint32_t)((wm * 64 + mt * 16 + aRowL) * PADG + aColL) * 2;
#pragma unroll
        for (int nt2 = 0; nt2 < 2; nt2++)
            bAddr[nt2] = sbB + (uint32_t)st * (ASTAGE_H * 2)
                       + (uint32_t)((wn * 32 + nt2 * 16 + bRowL) * PADG + bColL) * 2;

#pragma unroll
        for (int ks = 0; ks < 2; ks++) {
            const uint32_t off = (uint32_t)ks * 32;   // 16 halves
            uint32_t ah[4][4];
#pragma unroll
            for (int mt = 0; mt < 4; mt++)
                ldsm4(ah[mt][0], ah[mt][1], ah[mt][2], ah[mt][3], aAddr[mt] + off);
            uint32_t bf[2][4];
#pragma unroll
            for (int nt2 = 0; nt2 < 2; nt2++)
                ldsm4(bf[nt2][0], bf[nt2][1], bf[nt2][2], bf[nt2][3], bAddr[nt2] + off);
#pragma unroll
            for (int mt = 0; mt < 4; mt++)
#pragma unroll
                for (int nt2 = 0; nt2 < 2; nt2++) {
                    mma16(c[mt][nt2 * 2 + 0], ah[mt], &bf[nt2][0]);
                    mma16(c[mt][nt2 * 2 + 1], ah[mt], &bf[nt2][2]);
                }
        }
    }
#undef ISSUE

    // epilogue
    const float* bias = (mat == 0) ? bq : ((mat == 1) ? bk : bv);
    __half* dstqk     = (mat == 0) ? g_q16 : g_k16;
    const bool rqk    = (mat != 2);
#pragma unroll
    for (int mt = 0; mt < 4; mt++) {
        const int m = m0 + wm * 64 + mt * 16 + lr;
#pragma unroll
        for (int nt = 0; nt < 4; nt++) {
            const int n = n0 + wn * 32 + nt * 8 + 2 * lc;
            const int hh = n >> 6, d = n & 63;
            const float b0 = bias[n], b1 = bias[n + 1];
#pragma unroll
            for (int half_ = 0; half_ < 2; half_++) {
                const int mm = m + half_ * 8;
                const int bi = mm >> 9, srow = mm & 511;
                float v0 = c[mt][nt][half_ * 2 + 0] + b0;
                float v1 = c[mt][nt][half_ * 2 + 1] + b1;
                if (rqk) {
                    __half2 hv = __floats2half2_rn(v0, v1);
                    *(__half2*)(dstqk + (((size_t)(bi * NH + hh)) * SEQ + srow) * DH + d) = hv;
                } else {
                    const float mv = mask[(size_t)bi * SEQ + srow];
                    __half* o = g_vt16 + ((size_t)(bi * NH + hh) * DH) * SEQ;
                    o[(size_t)d * SEQ + srow]       = __float2half(v0 * mv);
                    o[(size_t)(d + 1) * SEQ + srow] = __float2half(v1 * mv);
                }
            }
        }
    }
}

// ---------------------------------------------------------------------------
// Fused power-law attention, fp16 m16n8k16 + ldmatrix.
// 8 warps x 16 q-rows (q-tile 128); key-tile 32, TRIPLE-buffered cp.async,
// ONE syncthreads per tile. Q register-resident; phase1 accs feed phase2
// A-frags directly; V transposed [d][s].
// ---------------------------------------------------------------------------
#define KT 32
#define PADKH 72
#define PADVH 40
#define KBUF_H (KT * PADKH)
#define VBUF_H (DH * PADVH)

__global__ __launch_bounds__(256, 2) void attn_kernel(float* __restrict__ out)
{
    __shared__ __half Ks[3][KBUF_H];
    __shared__ __half Vs[3][VBUF_H];

    const int b  = blockIdx.z;
    const int h  = blockIdx.y;
    const int qt = blockIdx.x * 128;

    const __half* Qg = g_q16 + (((size_t)(b * NH + h)) * SEQ + qt) * DH;
    const __half* Kg = g_k16 + ((size_t)(b * NH + h)) * SEQ * DH;
    const __half* Vg = g_vt16 + ((size_t)(b * NH + h)) * DH * SEQ;   // [d][s]

    const int tid  = threadIdx.x;
    const int lane = tid & 31;
    const int wid  = tid >> 5;
    const int lr   = lane >> 2;
    const int lc   = lane & 3;

    const int krow = tid >> 3;
    const int ksg  = (tid & 7) * 8;
    const __half* KgR = Kg + (size_t)krow * DH + ksg;
    const uint32_t sK = smem_u32(&Ks[0][0]) + (uint32_t)(krow * PADKH + ksg) * 2;

    const int vrow = tid >> 2;
    const int vsg  = (tid & 3) * 8;
    const __half* VgR = Vg + (size_t)vrow * SEQ + vsg;
    const uint32_t sV = smem_u32(&Vs[0][0]) + (uint32_t)(vrow * PADVH + vsg) * 2;

    const int l7 = lane & 7;
    const int bRowL = l7 + ((lane >> 4) & 1) * 8;
    const int bColL = ((lane >> 3) & 1) * 8;

#define ISSKV(kt_, buf_)                                                      \
    do {                                                                      \
        const __half* _k = KgR + (size_t)(kt_) * KT * DH;                     \
        const __half* _v = VgR + (kt_) * KT;                                  \
        uint32_t _ok = (uint32_t)(buf_) * (KBUF_H * 2);                       \
        uint32_t _ov = (uint32_t)(buf_) * (VBUF_H * 2);                       \
        cpa16(sK + _ok, _k);                                                  \
        cpa16(sV + _ov, _v);                                                  \
        cpa_commit();                                                         \
    } while (0)

    ISSKV(0, 0);
    ISSKV(1, 1);

    uint32_t qf[4][4];
    {
        const int r0 = wid * 16 + lr;
#pragma unroll
        for (int ks = 0; ks < 4; ks++) {
            const int dbase = ks * 16 + 2 * lc;
            qf[ks][0] = *(const uint32_t*)(Qg + (size_t)r0 * DH + dbase);
            qf[ks][1] = *(const uint32_t*)(Qg + (size_t)(r0 + 8) * DH + dbase);
            qf[ks][2] = *(const uint32_t*)(Qg + (size_t)r0 * DH + dbase + 8);
            qf[ks][3] = *(const uint32_t*)(Qg + (size_t)(r0 + 8) * DH + dbase + 8);
        }
    }

    const uint32_t kBase = smem_u32(&Ks[0][0]);
    const uint32_t vBase = smem_u32(&Vs[0][0]);

    float o[8][4];
#pragma unroll
    for (int j = 0; j < 8; j++)
#pragma unroll
        for (int q = 0; q < 4; q++) o[j][q] = 0.0f;
    float den0 = 0.0f, den1 = 0.0f;

    const int NKT = SEQ / KT;   // 16

    for (int kt = 0; kt < NKT; kt++) {
        cpa_wait<1>();           // tile kt arrived (positional: all but newest done)
        __syncthreads();         // all warps done with buffer being reused

        if (kt + 2 < NKT) ISSKV(kt + 2, (kt + 2) % 3);
        else cpa_commit();       // keep positional wait math exact at the tail

        const int buf = kt % 3;
        const uint32_t kb = kBase + (uint32_t)buf * (KBUF_H * 2);
        const uint32_t vb = vBase + (uint32_t)buf * (VBUF_H * 2);

        float s[4][4];
#pragma unroll
        for (int j = 0; j < 4; j++)
#pragma unroll
            for (int q = 0; q < 4; q++) s[j][q] = 0.0f;

        uint32_t kAddr0 = kb + (uint32_t)((bRowL) * PADKH + bColL) * 2;
        uint32_t kAddr1 = kb + (uint32_t)((16 + bRowL) * PADKH + bColL) * 2;
#pragma unroll
        for (int ks = 0; ks < 4; ks++) {
            const uint32_t off = (uint32_t)ks * 32;
            uint32_t f0[4], f1[4];
            ldsm4(f0[0], f0[1], f0[2], f0[3], kAddr0 + off);
            ldsm4(f1[0], f1[1], f1[2], f1[3], kAddr1 + off);
            mma16(s[0], qf[ks], &f0[0]);
            mma16(s[1], qf[ks], &f0[2]);
            mma16(s[2], qf[ks], &f1[0]);
            mma16(s[3], qf[ks], &f1[2]);
        }

        float u[4][4];
#pragma unroll
        for (int nt = 0; nt < 4; nt++) {
#pragma unroll
            for (int q = 0; q < 4; q++) {
                float t = fmaf(s[nt][q], 0.125f, 5.0f);
                u[nt][q] = t * t;
            }
            den0 += u[nt][0] + u[nt][1];
            den1 += u[nt][2] + u[nt][3];
        }

#pragma unroll
        for (int ksp = 0; ksp < 2; ksp++) {
            uint32_t af[4];
            af[0] = pkh2(u[2 * ksp][0],     u[2 * ksp][1]);
            af[1] = pkh2(u[2 * ksp][2],     u[2 * ksp][3]);
            af[2] = pkh2(u[2 * ksp + 1][0], u[2 * ksp + 1][1]);
            af[3] = pkh2(u[2 * ksp + 1][2], u[2 * ksp + 1][3]);
            const uint32_t coff = (uint32_t)ksp * 32;
#pragma unroll
            for (int dtp = 0; dtp < 4; dtp++) {
                uint32_t vAddr = vb + (uint32_t)((dtp * 16 + bRowL) * PADVH + bColL) * 2 + coff;
                uint32_t vf[4];
                ldsm4(vf[0], vf[1], vf[2], vf[3], vAddr);
                mma16(o[dtp * 2 + 0], af, &vf[0]);
                mma16(o[dtp * 2 + 1], af, &vf[2]);
            }
        }
    }
#undef ISSKV

    den0 += __shfl_xor_sync(0xFFFFFFFFu, den0, 1);
    den0 += __shfl_xor_sync(0xFFFFFFFFu, den0, 2);
    den1 += __shfl_xor_sync(0xFFFFFFFFu, den1, 1);
    den1 += __shfl_xor_sync(0xFFFFFFFFu, den1, 2);

    const float inv0 = 1.0f / (den0 + 1e-10f);
    const float inv1 = 1.0f / (den1 + 1e-10f);
    const int r0 = qt + wid * 16 + lr;
    float* o0 = out + ((size_t)b * SEQ + r0) * DM + h * DH;
    float* o1 = out + ((size_t)b * SEQ + r0 + 8) * DM + h * DH;
#pragma unroll
    for (int dt = 0; dt < 8; dt++) {
        const int d = dt * 8 + 2 * lc;
        *(float2*)(o0 + d) = make_float2(o[dt][0] * inv0, o[dt][1] * inv0);
        *(float2*)(o1 + d) = make_float2(o[dt][2] * inv1, o[dt][3] * inv1);
    }
}

// ---------------------------------------------------------------------------
extern "C" void kernel_launch(void* const* d_in, const int* in_sizes, int n_in,
                              void* d_out, int out_size)
{
    const float* hidden = (const float*)d_in[0];
    const float* mask   = (const float*)d_in[1];
    const float* Wq     = (const float*)d_in[2];
    const float* bq     = (const float*)d_in[3];
    const float* Wk     = (const float*)d_in[4];
    const float* bk     = (const float*)d_in[5];
    const float* Wv     = (const float*)d_in[6];
    const float* bv     = (const float*)d_in[7];
    float* out = (float*)d_out;

    const int BS = in_sizes[1];
    const int B  = BS / SEQ;
    const int M  = BS;

    cudaFuncSetAttribute(qkv_gemm_kernel,
                         cudaFuncAttributeMaxDynamicSharedMemorySize, GEMM_SMEM);

    int n8 = M * DM / 8;
    hhalf_kernel<<<(n8 + 255) / 256, 256>>>(hidden, n8);

    dim3 gw(DM / 32, DM / 32, 3);
    wsplit_kernel<<<gw, dim3(32, 8)>>>(Wq, Wk, Wv);

    dim3 gm(M / 128, 18);
    qkv_gemm_kernel<<<gm, 256, GEMM_SMEM>>>(bq, bk, bv, mask, M);

    dim3 g2(SEQ / 128, NH, B);
    attn_kernel<<<g2, 256>>>(out);
}